// round 16
// baseline (speedup 1.0000x reference)
#include <cuda_runtime.h>
#include <cstdint>

// NN upsample x2, NHWC fp32: (8,128,128,256) -> (8,256,256,256)
// Scatter, block=512 (best), ILP=4: each thread loads 4 INDEPENDENT input
// float4 (grid-quarter split, all streams coalesced), then issues 16 stores.
// Coarser chip-wide read/write bursts -> fewer DRAM bus turnarounds.
// All indexing in 32-bit (max index 33.5M < 2^31).

static constexpr int  W    = 128;
static constexpr int  C4   = 256 / 4;          // 64 float4 per pixel
static constexpr int  WO   = W * 2;            // 256
static constexpr unsigned N_IN4 = 8u * 128u * 128u * C4;  // 8,388,608
static constexpr unsigned QTR  = N_IN4 / 4;    // 2,097,152
static constexpr unsigned ROWS = (unsigned)WO * C4;       // 16384

__device__ __forceinline__ void scatter4(float4* __restrict__ out,
                                         unsigned idx, const float4& v)
{
    unsigned c4 = idx & (C4 - 1);
    unsigned t  = idx >> 6;                    // (b*H + h)*W + w
    unsigned w  = t & (W - 1);
    unsigned bh = t >> 7;                      // b*H + h

    unsigned o = (2u * bh * WO + 2u * w) * C4 + c4;

    out[o]             = v;   // (2h,   2w)
    out[o + C4]        = v;   // (2h,   2w+1)
    out[o + ROWS]      = v;   // (2h+1, 2w)
    out[o + ROWS + C4] = v;   // (2h+1, 2w+1)
}

__global__ __launch_bounds__(512)
void upsample2x_kernel(const float4* __restrict__ in, float4* __restrict__ out)
{
    unsigned i0 = blockIdx.x * blockDim.x + threadIdx.x;
    unsigned i1 = i0 + QTR;
    unsigned i2 = i0 + 2 * QTR;
    unsigned i3 = i0 + 3 * QTR;

    // 4 independent loads in flight before any store.
    float4 v0 = __ldg(in + i0);
    float4 v1 = __ldg(in + i1);
    float4 v2 = __ldg(in + i2);
    float4 v3 = __ldg(in + i3);

    // 16-store write burst.
    scatter4(out, i0, v0);
    scatter4(out, i1, v1);
    scatter4(out, i2, v2);
    scatter4(out, i3, v3);
}

extern "C" void kernel_launch(void* const* d_in, const int* in_sizes, int n_in,
                              void* d_out, int out_size)
{
    const float4* in  = (const float4*)d_in[0];
    float4*       out = (float4*)d_out;

    const int threads = 512;
    const unsigned blocks = QTR / threads;     // 4096
    upsample2x_kernel<<<blocks, threads>>>(in, out);
}